// round 8
// baseline (speedup 1.0000x reference)
#include <cuda_runtime.h>
#include <math.h>

#define Bz   4
#define Sq   4096
#define Hn   8
#define Dn   64
#define LNE  512          // H*D
#define TS   8            // tokens per GEMM tile == scan tile
#define NT   512          // Sq/TS
#define GN   16           // scan groups
#define GT   32           // tiles per group (GN*GT == NT)
#define RK   132          // row-major A stride (128 k + 4 pad, mult of 4)
#define FS   68           // Fs/Is stride (mult of 4)

// ---- scratch (allocation-free: __device__ globals) ----
__device__ float g_fg  [(size_t)Bz*Sq*LNE];
__device__ float g_igh [(size_t)Bz*Sq*LNE];
__device__ float g_tsum[(size_t)Bz*NT*LNE];
__device__ float g_toff[(size_t)Bz*NT*LNE];
__device__ float g_gsum[(size_t)Bz*GN*LNE];
__device__ float g_tA  [(size_t)Bz*NT*LNE];
__device__ float g_tB  [(size_t)Bz*NT*LNE];
__device__ float g_cIn [(size_t)Bz*NT*LNE];
__device__ float g_gA  [(size_t)Bz*GN*LNE];
__device__ float g_gB  [(size_t)Bz*GN*LNE];

__device__ __forceinline__ float sigm(float x){
    return __fdividef(1.f, 1.f + __expf(-x));
}

// ---- packed f32x2 helpers (PTX-only on Blackwell) ----
__device__ __forceinline__ unsigned long long pk2(float x, float y){
    unsigned long long r;
    asm("mov.b64 %0, {%1,%2};" : "=l"(r) : "f"(x), "f"(y));
    return r;
}
__device__ __forceinline__ void fma2(unsigned long long &d, unsigned long long a, unsigned long long b){
    asm("fma.rn.f32x2 %0, %1, %2, %3;" : "=l"(d) : "l"(a), "l"(b), "l"(d));
}
__device__ __forceinline__ float2 up2(unsigned long long v){
    float2 f;
    asm("mov.b64 {%0,%1}, %2;" : "=f"(f.x), "=f"(f.y) : "l"(v));
    return f;
}

// ---- cp.async helpers ----
__device__ __forceinline__ unsigned su32(const void* p){
    return (unsigned)__cvta_generic_to_shared(p);
}
__device__ __forceinline__ void cp16(unsigned dst, const void* src){
    asm volatile("cp.async.ca.shared.global [%0], [%1], 16;" :: "r"(dst), "l"(src));
}
__device__ __forceinline__ void cpcommit(){
    asm volatile("cp.async.commit_group;");
}
template<int N> __device__ __forceinline__ void cpwait(){
    asm volatile("cp.async.wait_group %0;" :: "n"(N));
}

// ============ cumsum chunked scan (exclusive, along S) ============
__global__ void k_tilesum(const float* __restrict__ x){
    int blk = blockIdx.x;            // b*NT + t
    int b = blk >> 9, t = blk & 511;
    int lane = threadIdx.x;
    const float* p = x + ((size_t)(b*Sq + t*TS))*LNE + lane;
    float s = 0.f;
    #pragma unroll
    for(int i=0;i<TS;i++) s += p[(size_t)i*LNE];
    g_tsum[(size_t)blk*LNE + lane] = s;
}

__global__ void k_gsum(){
    int blk = blockIdx.x;            // b*GN + g
    int b = blk >> 4, g = blk & 15;
    int lane = threadIdx.x;
    size_t base = ((size_t)b*NT + g*GT)*LNE + lane;
    float s = 0.f;
    #pragma unroll
    for(int i=0;i<GT;i++) s += g_tsum[base + (size_t)i*LNE];
    g_gsum[(size_t)blk*LNE + lane] = s;
}

// tile scan with fused group-prefix recompute
__global__ void k_tscan(){
    int blk = blockIdx.x;            // b*GN + g
    int b = blk >> 4, g = blk & 15;
    int lane = threadIdx.x;
    float run = 0.f;
    size_t gbase = ((size_t)b*GN)*LNE + lane;
    for(int i=0;i<g;i++) run += g_gsum[gbase + (size_t)i*LNE];
    size_t base = ((size_t)b*NT + g*GT)*LNE + lane;
    float v[GT];
    #pragma unroll
    for(int i=0;i<GT;i++) v[i] = g_tsum[base + (size_t)i*LNE];
    #pragma unroll
    for(int i=0;i<GT;i++){ g_toff[base + (size_t)i*LNE] = run; run += v[i]; }
}

// ============ LN + GEMM1 + gates + lgate tile partials ============
// block = (b, 8-token tile), 128 threads.
// A row-major: As[r][0..63]=x, As[r][64..127]=LN(csum), r = s*8+h.
// thread (tx,ty): rows ty*8..+7, gate cols j0=tx*4..+3 as {j, 64+j, 128+j}
#define W1C 8            // k-rows per W chunk (gemm1)
#define W1N 16           // chunks
__global__ __launch_bounds__(128, 2) void k_ln_gemm1(
    const float* __restrict__ x,  const float* __restrict__ Wh,
    const float* __restrict__ bh, const float* __restrict__ gamma,
    const float* __restrict__ beta)
{
    __shared__ __align__(16) float sbuf[8704];      // As (64*132), later Fs|Is
    __shared__ __align__(16) float Wb[2][W1C*192];  // double-buffered W chunks
    __shared__ float s_mean[TS], s_rstd[TS];
    float* As = sbuf;
    int blk = blockIdx.x;
    int b = blk >> 9, t = blk & 511;
    int tid = threadIdx.x;
    int s0 = t*TS;

    // G0: x tile -> As[r][k] via cp.async (8 float4/thread)
    const float4* xin = reinterpret_cast<const float4*>(x + ((size_t)(b*Sq + s0))*LNE);
    #pragma unroll
    for(int q=0;q<8;q++){
        int i = tid + q*128;
        int lin = i*4;
        int s = lin >> 9, lam = lin & 511, h = lam >> 6, k = lam & 63;
        cp16(su32(&As[(s*8+h)*RK + k]), xin + i);
    }
    cpcommit();
    // G1: W chunk 0 (384 float4, 3/thread)
    {
        const float4* wsrc = reinterpret_cast<const float4*>(Wh);
        #pragma unroll
        for(int j=0;j<3;j++)
            cp16(su32(&Wb[0][(tid + j*128)*4]), wsrc + tid + j*128);
    }
    cpcommit();
    cpwait<1>();          // x tile landed; W0 may still be in flight
    __syncthreads();

    // exclusive local cumsum + tile offset -> raw csum into As[r][64+k]
    #pragma unroll
    for(int q=0;q<4;q++){
        int lam = tid + q*128;
        int h = lam >> 6, k = lam & 63;
        float run = g_toff[((size_t)(b*NT + t))*LNE + lam];
        #pragma unroll
        for(int s=0;s<TS;s++){
            int r = s*8 + h;
            float xv = As[r*RK + k];
            As[r*RK + 64 + k] = run;
            run += xv;
        }
    }
    __syncthreads();

    // LN stats over 512 per s: warp w handles s = w and w+4
    {
        int w = tid >> 5, lanei = tid & 31;
        #pragma unroll
        for(int sv=0;sv<2;sv++){
            int s = w + sv*4;
            float sum = 0.f, sq = 0.f;
            #pragma unroll
            for(int j=0;j<16;j++){
                int idx = lanei + j*32;
                int h = idx >> 6, k = idx & 63;
                float v = As[(s*8+h)*RK + 64 + k];
                sum += v; sq += v*v;
            }
            #pragma unroll
            for(int o=16;o>0;o>>=1){
                sum += __shfl_xor_sync(0xffffffffu, sum, o);
                sq  += __shfl_xor_sync(0xffffffffu, sq,  o);
            }
            if(lanei==0){
                float m = sum * (1.f/512.f);
                float var = sq * (1.f/512.f) - m*m;
                s_mean[s] = m;
                s_rstd[s] = rsqrtf(var + 1e-5f);
            }
        }
    }
    __syncthreads();

    // normalize in place (+gamma/beta)
    #pragma unroll
    for(int q=0;q<32;q++){
        int idx = tid + q*128;
        int s = idx >> 9, lam = idx & 511, h = lam >> 6, k = lam & 63;
        int p = (s*8+h)*RK + 64 + k;
        float v = As[p];
        As[p] = (v - s_mean[s]) * s_rstd[s] * gamma[lam] + beta[lam];
    }

    // GEMM: rows r0..r0+7, gate cols {j0..j0+3} x {ig,fg,hd}; W from smem chunks
    int tx = tid & 15, ty = tid >> 4;
    int r0 = ty*8, j0 = tx*4;
    unsigned long long acc[3][8][2];
    #pragma unroll
    for(int g=0;g<3;g++)
        #pragma unroll
        for(int i=0;i<8;i++){ acc[g][i][0]=0ull; acc[g][i][1]=0ull; }

    for(int c=0;c<W1N;c++){
        cpwait<0>();               // chunk c landed
        __syncthreads();           // visible to all; prev compute on other buf done
        if(c+1 < W1N){             // prefetch chunk c+1 into the other buffer
            const float4* wsrc = reinterpret_cast<const float4*>(Wh + (c+1)*W1C*192);
            float* dst = Wb[(c+1)&1];
            #pragma unroll
            for(int j=0;j<3;j++)
                cp16(su32(dst + (tid + j*128)*4), wsrc + tid + j*128);
        }
        cpcommit();                // (empty group when c+1==W1N)

        const float* wc = Wb[c&1];
        #pragma unroll
        for(int kq=0;kq<W1C/4;kq++){
            int kl0 = kq*4;
            float4 av[8];
            #pragma unroll
            for(int i=0;i<8;i++)
                av[i] = *reinterpret_cast<const float4*>(&As[(r0+i)*RK + c*W1C + kl0]);
            #pragma unroll
            for(int kk=0;kk<4;kk++){
                int kl = kl0 + kk;
                ulonglong2 w0 = *reinterpret_cast<const ulonglong2*>(wc + kl*192 + j0);
                ulonglong2 w1 = *reinterpret_cast<const ulonglong2*>(wc + kl*192 + 64 + j0);
                ulonglong2 w2 = *reinterpret_cast<const ulonglong2*>(wc + kl*192 + 128 + j0);
                unsigned long long aa[8];
                #pragma unroll
                for(int i=0;i<8;i++){
                    float a = (kk==0)?av[i].x:(kk==1)?av[i].y:(kk==2)?av[i].z:av[i].w;
                    aa[i] = pk2(a, a);
                }
                #pragma unroll
                for(int i=0;i<8;i++){
                    fma2(acc[0][i][0], aa[i], w0.x); fma2(acc[0][i][1], aa[i], w0.y);
                    fma2(acc[1][i][0], aa[i], w1.x); fma2(acc[1][i][1], aa[i], w1.y);
                    fma2(acc[2][i][0], aa[i], w2.x); fma2(acc[2][i][1], aa[i], w2.y);
                }
            }
        }
    }
    __syncthreads();   // done reading As; sbuf becomes Fs|Is

    float* Fs = sbuf;            // [64][FS]
    float* Is = sbuf + 64*FS;    // [64][FS]
    float big[4], bfg[4], bhd[4];
    #pragma unroll
    for(int jj=0;jj<4;jj++){
        big[jj] = bh[j0+jj]; bfg[jj] = bh[64+j0+jj]; bhd[jj] = bh[128+j0+jj];
    }

    // gates in registers, write fg/igh to global + shared
    #pragma unroll
    for(int i=0;i<8;i++){
        int r = r0 + i, s = r >> 3, h = r & 7;
        float2 i01 = up2(acc[0][i][0]), i23 = up2(acc[0][i][1]);
        float2 f01 = up2(acc[1][i][0]), f23 = up2(acc[1][i][1]);
        float2 h01 = up2(acc[2][i][0]), h23 = up2(acc[2][i][1]);
        float ig[4] = {i01.x+big[0], i01.y+big[1], i23.x+big[2], i23.y+big[3]};
        float fr[4] = {f01.x+bfg[0], f01.y+bfg[1], f23.x+bfg[2], f23.y+bfg[3]};
        float hd[4] = {h01.x+bhd[0], h01.y+bhd[1], h23.x+bhd[2], h23.y+bhd[3]};
        float4 f4, g4;
        f4.x = sigm(fr[0]); f4.y = sigm(fr[1]); f4.z = sigm(fr[2]); f4.w = sigm(fr[3]);
        g4.x = sigm(ig[0])*fmaxf(hd[0],0.f);
        g4.y = sigm(ig[1])*fmaxf(hd[1],0.f);
        g4.z = sigm(ig[2])*fmaxf(hd[2],0.f);
        g4.w = sigm(ig[3])*fmaxf(hd[3],0.f);
        size_t gi = ((size_t)(b*Sq + s0 + s))*LNE + h*64 + j0;
        *reinterpret_cast<float4*>(&g_fg [gi]) = f4;
        *reinterpret_cast<float4*>(&g_igh[gi]) = g4;
        *reinterpret_cast<float4*>(&Fs[r*FS + j0]) = f4;
        *reinterpret_cast<float4*>(&Is[r*FS + j0]) = g4;
    }
    __syncthreads();

    // per-tile lgate partials: A = prod fg, B = fold(B*fg + igh) over s=0..7
    #pragma unroll
    for(int q=0;q<4;q++){
        int lam = tid + q*128;
        int h = lam >> 6, d = lam & 63;
        float A = 1.f, Bv = 0.f;
        #pragma unroll
        for(int s=0;s<TS;s++){
            int r = s*8 + h;
            float f = Fs[r*FS + d];
            float v = Is[r*FS + d];
            Bv = Bv*f + v;
            A *= f;
        }
        size_t ti = ((size_t)(b*NT + t))*LNE + lam;
        g_tA[ti] = A;
        g_tB[ti] = Bv;
    }
}

// ============ cell carry scan over tiles ============
__global__ void k_cgsum(){
    int blk = blockIdx.x;            // b*GN + g
    int b = blk >> 4, g = blk & 15;
    int lane = threadIdx.x;
    size_t base = ((size_t)b*NT + g*GT)*LNE + lane;
    float A = 1.f, Bv = 0.f;
    #pragma unroll
    for(int i=0;i<GT;i++){
        float a = g_tA[base + (size_t)i*LNE];
        float v = g_tB[base + (size_t)i*LNE];
        Bv = Bv*a + v;
        A *= a;
    }
    g_gA[(size_t)blk*LNE + lane] = A;
    g_gB[(size_t)blk*LNE + lane] = Bv;
}

// tile carry scan with fused group-prefix recompute
__global__ void k_ctscan(const float* __restrict__ icx){
    int blk = blockIdx.x;            // b*GN + g
    int b = blk >> 4, g = blk & 15;
    int lane = threadIdx.x;
    float c = icx[lane];
    size_t gbase = ((size_t)b*GN)*LNE + lane;
    for(int i=0;i<g;i++)
        c = g_gA[gbase + (size_t)i*LNE]*c + g_gB[gbase + (size_t)i*LNE];
    size_t base = ((size_t)b*NT + g*GT)*LNE + lane;
    #pragma unroll
    for(int i=0;i<GT;i++){
        g_cIn[base + (size_t)i*LNE] = c;
        c = g_tA[base + (size_t)i*LNE]*c + g_tB[base + (size_t)i*LNE];
    }
}

// ============ GEMM2 (og) + cell recompute + output ============
// 64 threads: thread (tx,ty): rows ty*8..+7, cols c0=tx*8..+7
#define W2C 16           // k-rows per W chunk (gemm2)
#define W2N 8            // chunks
__global__ __launch_bounds__(64, 3) void k_gemm2(
    const float* __restrict__ x, const float* __restrict__ Wo,
    const float* __restrict__ bo, float* __restrict__ out)
{
    __shared__ __align__(16) float As[64*RK];
    __shared__ __align__(16) float Wb[2][W2C*64];
    int blk = blockIdx.x;
    int b = blk >> 9, t = blk & 511;
    int tid = threadIdx.x;
    int s0 = t*TS;

    // G0: x tile via cp.async (16 float4/thread)
    const float4* xin = reinterpret_cast<const float4*>(x + ((size_t)(b*Sq + s0))*LNE);
    #pragma unroll
    for(int q=0;q<16;q++){
        int i = tid + q*64;
        int lin = i*4;
        int s = lin >> 9, lam = lin & 511, h = lam >> 6, k = lam & 63;
        cp16(su32(&As[(s*8+h)*RK + k]), xin + i);
    }
    cpcommit();
    // G1: W chunk 0 (256 float4, 4/thread)
    {
        const float4* wsrc = reinterpret_cast<const float4*>(Wo);
        #pragma unroll
        for(int j=0;j<4;j++)
            cp16(su32(&Wb[0][(tid + j*64)*4]), wsrc + tid + j*64);
    }
    cpcommit();

    // recompute cell from carry + fg/igh -> As[r][64+k] (overlaps cp.async)
    #pragma unroll
    for(int q=0;q<8;q++){
        int lam = tid + q*64;
        int h = lam >> 6, k = lam & 63;
        float c = g_cIn[((size_t)(b*NT + t))*LNE + lam];
        size_t idx = ((size_t)(b*Sq + s0))*LNE + lam;
        #pragma unroll
        for(int s=0;s<TS;s++){
            c = g_fg[idx]*c + g_igh[idx];
            As[(s*8+h)*RK + 64 + k] = c;
            idx += LNE;
        }
    }

    int tx = tid & 7, ty = tid >> 3;
    int r0 = ty*8, c0 = tx*8;
    unsigned long long acc[8][4];
    #pragma unroll
    for(int i=0;i<8;i++)
        #pragma unroll
        for(int j=0;j<4;j++) acc[i][j] = 0ull;

    for(int c=0;c<W2N;c++){
        cpwait<0>();
        __syncthreads();
        if(c+1 < W2N){
            const float4* wsrc = reinterpret_cast<const float4*>(Wo + (c+1)*W2C*64);
            float* dst = Wb[(c+1)&1];
            #pragma unroll
            for(int j=0;j<4;j++)
                cp16(su32(dst + (tid + j*64)*4), wsrc + tid + j*64);
        }
        cpcommit();

        const float* wc = Wb[c&1];
        #pragma unroll
        for(int kq=0;kq<W2C/4;kq++){
            int kl0 = kq*4;
            float4 av[8];
            #pragma unroll
            for(int i=0;i<8;i++)
                av[i] = *reinterpret_cast<const float4*>(&As[(r0+i)*RK + c*W2C + kl0]);
            #pragma unroll
            for(int kk=0;kk<4;kk++){
                int kl = kl0 + kk;
                ulonglong2 wA = *reinterpret_cast<const ulonglong2*>(wc + kl*64 + c0);
                ulonglong2 wB = *reinterpret_cast<const ulonglong2*>(wc + kl*64 + c0 + 4);
                unsigned long long aa[8];
                #pragma unroll
                for(int i=0;i<8;i++){
                    float a = (kk==0)?av[i].x:(kk==1)?av[i].y:(kk==2)?av[i].z:av[i].w;
                    aa[i] = pk2(a, a);
                }
                #pragma unroll
                for(int i=0;i<8;i++){
                    fma2(acc[i][0], aa[i], wA.x); fma2(acc[i][1], aa[i], wA.y);
                    fma2(acc[i][2], aa[i], wB.x); fma2(acc[i][3], aa[i], wB.y);
                }
            }
        }
    }

    float bo8[8];
    #pragma unroll
    for(int j=0;j<8;j++) bo8[j] = bo[c0+j];

    #pragma unroll
    for(int i=0;i<8;i++){
        int r = r0 + i, s = r >> 3, h = r & 7;
        float2 v0 = up2(acc[i][0]), v1 = up2(acc[i][1]);
        float2 v2 = up2(acc[i][2]), v3 = up2(acc[i][3]);
        float og[8] = {
            sigm(v0.x + bo8[0]), sigm(v0.y + bo8[1]),
            sigm(v1.x + bo8[2]), sigm(v1.y + bo8[3]),
            sigm(v2.x + bo8[4]), sigm(v2.y + bo8[5]),
            sigm(v3.x + bo8[6]), sigm(v3.y + bo8[7])
        };
        float4 cvA = *reinterpret_cast<const float4*>(&As[r*RK + 64 + c0]);
        float4 cvB = *reinterpret_cast<const float4*>(&As[r*RK + 64 + c0 + 4]);
        float* dst = out + (((size_t)(b*Sq + s0 + s)*Hn + h)*64) + c0;
        *reinterpret_cast<float4*>(dst) =
            make_float4(og[0]*cvA.x, og[1]*cvA.y, og[2]*cvA.z, og[3]*cvA.w);
        *reinterpret_cast<float4*>(dst + 4) =
            make_float4(og[4]*cvB.x, og[5]*cvB.y, og[6]*cvB.z, og[7]*cvB.w);
    }
}

extern "C" void kernel_launch(void* const* d_in, const int* in_sizes, int n_in,
                              void* d_out, int out_size)
{
    const float* x     = (const float*)d_in[0];
    const float* Wh    = (const float*)d_in[1];
    const float* bh    = (const float*)d_in[2];
    const float* Wo    = (const float*)d_in[3];
    const float* bo    = (const float*)d_in[4];
    const float* gamma = (const float*)d_in[5];
    const float* beta  = (const float*)d_in[6];
    const float* icx   = (const float*)d_in[7];
    float* out = (float*)d_out;

    k_tilesum <<<Bz*NT, 512>>>(x);
    k_gsum    <<<Bz*GN, 512>>>();
    k_tscan   <<<Bz*GN, 512>>>();
    k_ln_gemm1<<<Bz*NT, 128>>>(x, Wh, bh, gamma, beta);
    k_cgsum   <<<Bz*GN, 512>>>();
    k_ctscan  <<<Bz*GN, 512>>>(icx);
    k_gemm2   <<<Bz*NT, 64>>>(x, Wo, bo, out);
}

// round 9
// speedup vs baseline: 1.1294x; 1.1294x over previous
#include <cuda_runtime.h>
#include <math.h>

#define Bz   4
#define Sq   4096
#define Hn   8
#define Dn   64
#define LNE  512          // H*D
#define TS   8            // tokens per GEMM tile == scan tile
#define NT   512          // Sq/TS
#define GN   16           // scan groups
#define GT   32           // tiles per group (GN*GT == NT)
#define RK   132          // row-major A stride (128 k + 4 pad, mult of 4)
#define FS   68           // Fs/Is stride (mult of 4)

// ---- scratch (allocation-free: __device__ globals) ----
__device__ float g_fg  [(size_t)Bz*Sq*LNE];
__device__ float g_igh [(size_t)Bz*Sq*LNE];
__device__ float g_tsum[(size_t)Bz*NT*LNE];
__device__ float g_toff[(size_t)Bz*NT*LNE];
__device__ float g_gsum[(size_t)Bz*GN*LNE];
__device__ float g_tA  [(size_t)Bz*NT*LNE];
__device__ float g_tB  [(size_t)Bz*NT*LNE];
__device__ float g_cIn [(size_t)Bz*NT*LNE];
__device__ float g_gA  [(size_t)Bz*GN*LNE];
__device__ float g_gB  [(size_t)Bz*GN*LNE];

// sigmoid via HW tanh: sigma(x) = 0.5*tanh(x/2) + 0.5  (1 MUFU instead of 2)
__device__ __forceinline__ float sigm(float x){
    float t;
    asm("tanh.approx.f32 %0, %1;" : "=f"(t) : "f"(x*0.5f));
    return fmaf(t, 0.5f, 0.5f);
}

// ---- packed f32x2 helpers (PTX-only on Blackwell) ----
__device__ __forceinline__ unsigned long long pk2(float x, float y){
    unsigned long long r;
    asm("mov.b64 %0, {%1,%2};" : "=l"(r) : "f"(x), "f"(y));
    return r;
}
__device__ __forceinline__ void fma2(unsigned long long &d, unsigned long long a, unsigned long long b){
    asm("fma.rn.f32x2 %0, %1, %2, %3;" : "=l"(d) : "l"(a), "l"(b), "l"(d));
}
__device__ __forceinline__ float2 up2(unsigned long long v){
    float2 f;
    asm("mov.b64 {%0,%1}, %2;" : "=f"(f.x), "=f"(f.y) : "l"(v));
    return f;
}

// ---- cp.async helpers ----
__device__ __forceinline__ unsigned su32(const void* p){
    return (unsigned)__cvta_generic_to_shared(p);
}
__device__ __forceinline__ void cp16(unsigned dst, const void* src){
    asm volatile("cp.async.ca.shared.global [%0], [%1], 16;" :: "r"(dst), "l"(src));
}
__device__ __forceinline__ void cpcommit(){
    asm volatile("cp.async.commit_group;");
}
template<int N> __device__ __forceinline__ void cpwait(){
    asm volatile("cp.async.wait_group %0;" :: "n"(N));
}

// ============ cumsum chunked scan (exclusive, along S) ============
__global__ void k_tilesum(const float* __restrict__ x){
    int blk = blockIdx.x;            // b*NT + t
    int b = blk >> 9, t = blk & 511;
    int lane = threadIdx.x;
    const float* p = x + ((size_t)(b*Sq + t*TS))*LNE + lane;
    float s = 0.f;
    #pragma unroll
    for(int i=0;i<TS;i++) s += p[(size_t)i*LNE];
    g_tsum[(size_t)blk*LNE + lane] = s;
}

__global__ void k_gsum(){
    int blk = blockIdx.x;            // b*GN + g
    int b = blk >> 4, g = blk & 15;
    int lane = threadIdx.x;
    size_t base = ((size_t)b*NT + g*GT)*LNE + lane;
    float s = 0.f;
    #pragma unroll
    for(int i=0;i<GT;i++) s += g_tsum[base + (size_t)i*LNE];
    g_gsum[(size_t)blk*LNE + lane] = s;
}

// tile scan with fused group-prefix recompute
__global__ void k_tscan(){
    int blk = blockIdx.x;            // b*GN + g
    int b = blk >> 4, g = blk & 15;
    int lane = threadIdx.x;
    float run = 0.f;
    size_t gbase = ((size_t)b*GN)*LNE + lane;
    for(int i=0;i<g;i++) run += g_gsum[gbase + (size_t)i*LNE];
    size_t base = ((size_t)b*NT + g*GT)*LNE + lane;
    float v[GT];
    #pragma unroll
    for(int i=0;i<GT;i++) v[i] = g_tsum[base + (size_t)i*LNE];
    #pragma unroll
    for(int i=0;i<GT;i++){ g_toff[base + (size_t)i*LNE] = run; run += v[i]; }
}

// ============ LN + GEMM1 + gates + lgate tile partials ============
// block = (b, 8-token tile), 128 threads.
// A row-major: As[r][0..63]=x, As[r][64..127]=LN(csum), r = s*8+h.
// thread (tx,ty): rows ty*8..+7, gate cols j0=tx*4..+3 as {j, 64+j, 128+j}
#define W1C 8            // k-rows per W chunk (gemm1)
#define W1N 16           // chunks
__global__ __launch_bounds__(128, 2) void k_ln_gemm1(
    const float* __restrict__ x,  const float* __restrict__ Wh,
    const float* __restrict__ bh, const float* __restrict__ gamma,
    const float* __restrict__ beta)
{
    __shared__ __align__(16) float sbuf[8704];      // As (64*132), later Fs|Is
    __shared__ __align__(16) float Wb[2][W1C*192];  // double-buffered W chunks
    __shared__ float redS[4][TS], redQ[4][TS];
    __shared__ float s_mean[TS], s_rstd[TS];
    float* As = sbuf;
    int blk = blockIdx.x;
    int b = blk >> 9, t = blk & 511;
    int tid = threadIdx.x;
    int s0 = t*TS;

    // G0: x tile -> As[r][k] via cp.async (8 float4/thread)
    const float4* xin = reinterpret_cast<const float4*>(x + ((size_t)(b*Sq + s0))*LNE);
    #pragma unroll
    for(int q=0;q<8;q++){
        int i = tid + q*128;
        int lin = i*4;
        int s = lin >> 9, lam = lin & 511, h = lam >> 6, k = lam & 63;
        cp16(su32(&As[(s*8+h)*RK + k]), xin + i);
    }
    cpcommit();
    // G1: W chunk 0 (384 float4, 3/thread)
    {
        const float4* wsrc = reinterpret_cast<const float4*>(Wh);
        #pragma unroll
        for(int j=0;j<3;j++)
            cp16(su32(&Wb[0][(tid + j*128)*4]), wsrc + tid + j*128);
    }
    cpcommit();
    cpwait<1>();          // x tile landed; W0 may still be in flight
    __syncthreads();

    // exclusive cumsum held in REGISTERS + fused LN-stat accumulation
    float cs[4][TS];
    float psum[TS], psq[TS];
    #pragma unroll
    for(int s=0;s<TS;s++){ psum[s]=0.f; psq[s]=0.f; }
    #pragma unroll
    for(int q=0;q<4;q++){
        int lam = tid + q*128;
        int h = lam >> 6, k = lam & 63;
        float run = g_toff[((size_t)(b*NT + t))*LNE + lam];
        #pragma unroll
        for(int s=0;s<TS;s++){
            float xv = As[(s*8+h)*RK + k];
            cs[q][s] = run;
            psum[s] += run;
            psq[s]  += run*run;
            run += xv;
        }
    }
    // warp reduce, then cross-warp via tiny smem
    #pragma unroll
    for(int o=16;o>0;o>>=1){
        #pragma unroll
        for(int s=0;s<TS;s++){
            psum[s] += __shfl_xor_sync(0xffffffffu, psum[s], o);
            psq[s]  += __shfl_xor_sync(0xffffffffu, psq[s],  o);
        }
    }
    {
        int w = tid >> 5, lanei = tid & 31;
        if(lanei==0){
            #pragma unroll
            for(int s=0;s<TS;s++){ redS[w][s] = psum[s]; redQ[w][s] = psq[s]; }
        }
    }
    __syncthreads();
    if(tid < TS){
        float sum = redS[0][tid] + redS[1][tid] + redS[2][tid] + redS[3][tid];
        float sq  = redQ[0][tid] + redQ[1][tid] + redQ[2][tid] + redQ[3][tid];
        float m = sum * (1.f/512.f);
        float var = sq * (1.f/512.f) - m*m;
        s_mean[tid] = m;
        s_rstd[tid] = rsqrtf(var + 1e-5f);
    }
    __syncthreads();

    // write normalized csum directly (no extra read pass)
    #pragma unroll
    for(int q=0;q<4;q++){
        int lam = tid + q*128;
        int h = lam >> 6, k = lam & 63;
        float ga = gamma[lam], be = beta[lam];
        #pragma unroll
        for(int s=0;s<TS;s++){
            As[(s*8+h)*RK + 64 + k] =
                (cs[q][s] - s_mean[s]) * s_rstd[s] * ga + be;
        }
    }

    // GEMM: rows r0..r0+7, gate cols {j0..j0+3} x {ig,fg,hd}; W from smem chunks
    int tx = tid & 15, ty = tid >> 4;
    int r0 = ty*8, j0 = tx*4;
    unsigned long long acc[3][8][2];
    #pragma unroll
    for(int g=0;g<3;g++)
        #pragma unroll
        for(int i=0;i<8;i++){ acc[g][i][0]=0ull; acc[g][i][1]=0ull; }

    for(int c=0;c<W1N;c++){
        cpwait<0>();               // chunk c landed
        __syncthreads();           // visible to all; prev compute on other buf done
        if(c+1 < W1N){             // prefetch chunk c+1 into the other buffer
            const float4* wsrc = reinterpret_cast<const float4*>(Wh + (c+1)*W1C*192);
            float* dst = Wb[(c+1)&1];
            #pragma unroll
            for(int j=0;j<3;j++)
                cp16(su32(dst + (tid + j*128)*4), wsrc + tid + j*128);
        }
        cpcommit();                // (empty group when c+1==W1N)

        const float* wc = Wb[c&1];
        #pragma unroll
        for(int kq=0;kq<W1C/4;kq++){
            int kl0 = kq*4;
            float4 av[8];
            #pragma unroll
            for(int i=0;i<8;i++)
                av[i] = *reinterpret_cast<const float4*>(&As[(r0+i)*RK + c*W1C + kl0]);
            #pragma unroll
            for(int kk=0;kk<4;kk++){
                int kl = kl0 + kk;
                ulonglong2 w0 = *reinterpret_cast<const ulonglong2*>(wc + kl*192 + j0);
                ulonglong2 w1 = *reinterpret_cast<const ulonglong2*>(wc + kl*192 + 64 + j0);
                ulonglong2 w2 = *reinterpret_cast<const ulonglong2*>(wc + kl*192 + 128 + j0);
                unsigned long long aa[8];
                #pragma unroll
                for(int i=0;i<8;i++){
                    float a = (kk==0)?av[i].x:(kk==1)?av[i].y:(kk==2)?av[i].z:av[i].w;
                    aa[i] = pk2(a, a);
                }
                #pragma unroll
                for(int i=0;i<8;i++){
                    fma2(acc[0][i][0], aa[i], w0.x); fma2(acc[0][i][1], aa[i], w0.y);
                    fma2(acc[1][i][0], aa[i], w1.x); fma2(acc[1][i][1], aa[i], w1.y);
                    fma2(acc[2][i][0], aa[i], w2.x); fma2(acc[2][i][1], aa[i], w2.y);
                }
            }
        }
    }
    __syncthreads();   // done reading As; sbuf becomes Fs|Is

    float* Fs = sbuf;            // [64][FS]
    float* Is = sbuf + 64*FS;    // [64][FS]
    float big[4], bfg[4], bhd[4];
    #pragma unroll
    for(int jj=0;jj<4;jj++){
        big[jj] = bh[j0+jj]; bfg[jj] = bh[64+j0+jj]; bhd[jj] = bh[128+j0+jj];
    }

    // gates in registers, write fg/igh to global + shared
    #pragma unroll
    for(int i=0;i<8;i++){
        int r = r0 + i, s = r >> 3, h = r & 7;
        float2 i01 = up2(acc[0][i][0]), i23 = up2(acc[0][i][1]);
        float2 f01 = up2(acc[1][i][0]), f23 = up2(acc[1][i][1]);
        float2 h01 = up2(acc[2][i][0]), h23 = up2(acc[2][i][1]);
        float ig[4] = {i01.x+big[0], i01.y+big[1], i23.x+big[2], i23.y+big[3]};
        float fr[4] = {f01.x+bfg[0], f01.y+bfg[1], f23.x+bfg[2], f23.y+bfg[3]};
        float hd[4] = {h01.x+bhd[0], h01.y+bhd[1], h23.x+bhd[2], h23.y+bhd[3]};
        float4 f4, g4;
        f4.x = sigm(fr[0]); f4.y = sigm(fr[1]); f4.z = sigm(fr[2]); f4.w = sigm(fr[3]);
        g4.x = sigm(ig[0])*fmaxf(hd[0],0.f);
        g4.y = sigm(ig[1])*fmaxf(hd[1],0.f);
        g4.z = sigm(ig[2])*fmaxf(hd[2],0.f);
        g4.w = sigm(ig[3])*fmaxf(hd[3],0.f);
        size_t gi = ((size_t)(b*Sq + s0 + s))*LNE + h*64 + j0;
        *reinterpret_cast<float4*>(&g_fg [gi]) = f4;
        *reinterpret_cast<float4*>(&g_igh[gi]) = g4;
        *reinterpret_cast<float4*>(&Fs[r*FS + j0]) = f4;
        *reinterpret_cast<float4*>(&Is[r*FS + j0]) = g4;
    }
    __syncthreads();

    // per-tile lgate partials: A = prod fg, B = fold(B*fg + igh) over s=0..7
    #pragma unroll
    for(int q=0;q<4;q++){
        int lam = tid + q*128;
        int h = lam >> 6, d = lam & 63;
        float A = 1.f, Bv = 0.f;
        #pragma unroll
        for(int s=0;s<TS;s++){
            int r = s*8 + h;
            float f = Fs[r*FS + d];
            float v = Is[r*FS + d];
            Bv = Bv*f + v;
            A *= f;
        }
        size_t ti = ((size_t)(b*NT + t))*LNE + lam;
        g_tA[ti] = A;
        g_tB[ti] = Bv;
    }
}

// ============ cell carry scan over tiles ============
__global__ void k_cgsum(){
    int blk = blockIdx.x;            // b*GN + g
    int b = blk >> 4, g = blk & 15;
    int lane = threadIdx.x;
    size_t base = ((size_t)b*NT + g*GT)*LNE + lane;
    float A = 1.f, Bv = 0.f;
    #pragma unroll
    for(int i=0;i<GT;i++){
        float a = g_tA[base + (size_t)i*LNE];
        float v = g_tB[base + (size_t)i*LNE];
        Bv = Bv*a + v;
        A *= a;
    }
    g_gA[(size_t)blk*LNE + lane] = A;
    g_gB[(size_t)blk*LNE + lane] = Bv;
}

// tile carry scan with fused group-prefix recompute
__global__ void k_ctscan(const float* __restrict__ icx){
    int blk = blockIdx.x;            // b*GN + g
    int b = blk >> 4, g = blk & 15;
    int lane = threadIdx.x;
    float c = icx[lane];
    size_t gbase = ((size_t)b*GN)*LNE + lane;
    for(int i=0;i<g;i++)
        c = g_gA[gbase + (size_t)i*LNE]*c + g_gB[gbase + (size_t)i*LNE];
    size_t base = ((size_t)b*NT + g*GT)*LNE + lane;
    #pragma unroll
    for(int i=0;i<GT;i++){
        g_cIn[base + (size_t)i*LNE] = c;
        c = g_tA[base + (size_t)i*LNE]*c + g_tB[base + (size_t)i*LNE];
    }
}

// ============ GEMM2 (og) + cell recompute + output ============
// 128 threads: thread (tx,ty): rows ty*8..+7, cols c0=tx*4..+3
#define W2C 16           // k-rows per W chunk (gemm2)
#define W2N 8            // chunks
__global__ __launch_bounds__(128, 2) void k_gemm2(
    const float* __restrict__ x, const float* __restrict__ Wo,
    const float* __restrict__ bo, float* __restrict__ out)
{
    __shared__ __align__(16) float As[64*RK];
    __shared__ __align__(16) float Wb[2][W2C*64];
    int blk = blockIdx.x;
    int b = blk >> 9, t = blk & 511;
    int tid = threadIdx.x;
    int s0 = t*TS;

    // G0: x tile via cp.async (8 float4/thread)
    const float4* xin = reinterpret_cast<const float4*>(x + ((size_t)(b*Sq + s0))*LNE);
    #pragma unroll
    for(int q=0;q<8;q++){
        int i = tid + q*128;
        int lin = i*4;
        int s = lin >> 9, lam = lin & 511, h = lam >> 6, k = lam & 63;
        cp16(su32(&As[(s*8+h)*RK + k]), xin + i);
    }
    cpcommit();
    // G1: W chunk 0 (256 float4, 2/thread)
    {
        const float4* wsrc = reinterpret_cast<const float4*>(Wo);
        cp16(su32(&Wb[0][tid*4]), wsrc + tid);
        cp16(su32(&Wb[0][(tid+128)*4]), wsrc + tid + 128);
    }
    cpcommit();

    // recompute cell from carry + fg/igh -> As[r][64+k] (overlaps cp.async)
    #pragma unroll
    for(int q=0;q<4;q++){
        int lam = tid + q*128;
        int h = lam >> 6, k = lam & 63;
        float c = g_cIn[((size_t)(b*NT + t))*LNE + lam];
        size_t idx = ((size_t)(b*Sq + s0))*LNE + lam;
        #pragma unroll
        for(int s=0;s<TS;s++){
            c = g_fg[idx]*c + g_igh[idx];
            As[(s*8+h)*RK + 64 + k] = c;
            idx += LNE;
        }
    }

    int tx = tid & 15, ty = tid >> 4;
    int r0 = ty*8, c0 = tx*4;
    unsigned long long acc[8][2];
    #pragma unroll
    for(int i=0;i<8;i++){ acc[i][0]=0ull; acc[i][1]=0ull; }

    for(int c=0;c<W2N;c++){
        cpwait<0>();
        __syncthreads();
        if(c+1 < W2N){
            const float4* wsrc = reinterpret_cast<const float4*>(Wo + (c+1)*W2C*64);
            float* dst = Wb[(c+1)&1];
            cp16(su32(dst + tid*4), wsrc + tid);
            cp16(su32(dst + (tid+128)*4), wsrc + tid + 128);
        }
        cpcommit();

        const float* wc = Wb[c&1];
        #pragma unroll
        for(int kq=0;kq<W2C/4;kq++){
            int kl0 = kq*4;
            float4 av[8];
            #pragma unroll
            for(int i=0;i<8;i++)
                av[i] = *reinterpret_cast<const float4*>(&As[(r0+i)*RK + c*W2C + kl0]);
            #pragma unroll
            for(int kk=0;kk<4;kk++){
                int kl = kl0 + kk;
                ulonglong2 w = *reinterpret_cast<const ulonglong2*>(wc + kl*64 + c0);
                unsigned long long aa[8];
                #pragma unroll
                for(int i=0;i<8;i++){
                    float a = (kk==0)?av[i].x:(kk==1)?av[i].y:(kk==2)?av[i].z:av[i].w;
                    aa[i] = pk2(a, a);
                }
                #pragma unroll
                for(int i=0;i<8;i++){
                    fma2(acc[i][0], aa[i], w.x); fma2(acc[i][1], aa[i], w.y);
                }
            }
        }
    }

    float bo4[4];
    #pragma unroll
    for(int j=0;j<4;j++) bo4[j] = bo[c0+j];

    #pragma unroll
    for(int i=0;i<8;i++){
        int r = r0 + i, s = r >> 3, h = r & 7;
        float2 v0 = up2(acc[i][0]), v1 = up2(acc[i][1]);
        float o0 = sigm(v0.x + bo4[0]);
        float o1 = sigm(v0.y + bo4[1]);
        float o2 = sigm(v1.x + bo4[2]);
        float o3 = sigm(v1.y + bo4[3]);
        float4 cv = *reinterpret_cast<const float4*>(&As[r*RK + 64 + c0]);
        float* dst = out + (((size_t)(b*Sq + s0 + s)*Hn + h)*64) + c0;
        *reinterpret_cast<float4*>(dst) =
            make_float4(o0*cv.x, o1*cv.y, o2*cv.z, o3*cv.w);
    }
}

extern "C" void kernel_launch(void* const* d_in, const int* in_sizes, int n_in,
                              void* d_out, int out_size)
{
    const float* x     = (const float*)d_in[0];
    const float* Wh    = (const float*)d_in[1];
    const float* bh    = (const float*)d_in[2];
    const float* Wo    = (const float*)d_in[3];
    const float* bo    = (const float*)d_in[4];
    const float* gamma = (const float*)d_in[5];
    const float* beta  = (const float*)d_in[6];
    const float* icx   = (const float*)d_in[7];
    float* out = (float*)d_out;

    k_tilesum <<<Bz*NT, 512>>>(x);
    k_gsum    <<<Bz*GN, 512>>>();
    k_tscan   <<<Bz*GN, 512>>>();
    k_ln_gemm1<<<Bz*NT, 128>>>(x, Wh, bh, gamma, beta);
    k_cgsum   <<<Bz*GN, 512>>>();
    k_ctscan  <<<Bz*GN, 512>>>(icx);
    k_gemm2   <<<Bz*NT, 128>>>(x, Wo, bo, out);
}